// round 15
// baseline (speedup 1.0000x reference)
#include <cuda_runtime.h>
#include <cuda_bf16.h>

// MaskedPooling: out[b,d] = sum_t x[b,t,d]*keep[b,t] / sum_t keep[b,t]
// x: [32,4096,512] f32, mask: [32,4096] int32 (nonzero = excluded).
// R15: warp-per-row streams. Previous kernels split each row's 2KB across the
// 4 warps (per-warp LDG streams 2KB-STRIDED, rows arriving at L2/DRAM as 4
// scattered 512B fragments) -> suspected cause of the ~60% DRAM ceiling.
// Now warp w owns kept rows w, w+4, ... and reads each row as 4 back-to-back
// contiguous LDG.128 (one tight 2KB burst). Depth-1 pipeline kept. No
// predicated tail (each warp loops exactly its own count -> zero waste reads).
// 8KB smem cross-warp reduction; fused last-CTA finalize unchanged.

#define B_DIM 32
#define T_DIM 4096
#define D_DIM 512
#define S_SPLIT 32
#define ROWS (T_DIM / S_SPLIT)   // 128 rows per chunk
#define TPB 128
#define DSTRIDE (D_DIM / 4)      // 128 float4 per row
#define ROW_BYTES (D_DIM * 4)    // 2048

__device__ float g_partial[B_DIM * S_SPLIT * D_DIM];  // 2 MB scratch
__device__ float g_count[B_DIM * S_SPLIT];
__device__ int   g_sem[B_DIM];                        // zero-init; self-resetting

#define ACC4(A, V) do { (A).x += (V).x; (A).y += (V).y; (A).z += (V).z; (A).w += (V).w; } while (0)

__global__ __launch_bounds__(TPB, 7) void mp_fused_kernel(
    const float* __restrict__ x, const int* __restrict__ mask,
    float* __restrict__ out) {
    const int s = blockIdx.x;   // T-chunk
    const int b = blockIdx.y;   // batch
    const int tid = threadIdx.x;
    const int lane = tid & 31;
    const int wid = tid >> 5;
    const int t0 = s * ROWS;

    __shared__ int m[ROWS];
    __shared__ int offbuf[ROWS];          // byte offsets of kept rows
    __shared__ int wcnt[5];
    __shared__ float4 sacc[4][TPB];       // 8 KB cross-warp reduction staging
    __shared__ bool isLast;

    // stage mask chunk (128 int32 = 512 B)
    if (tid < ROWS / 4) {
        reinterpret_cast<int4*>(m)[tid] =
            reinterpret_cast<const int4*>(mask + b * T_DIM + t0)[tid];
    }
    __syncthreads();

    // compact kept-row byte offsets: single ballot round (ROWS == TPB)
    bool kflag = (m[tid] == 0);
    unsigned bal = __ballot_sync(0xffffffffu, kflag);
    if (lane == 0) wcnt[wid] = __popc(bal);
    __syncthreads();
    if (tid == 0) {
        int sum = 0;
        #pragma unroll
        for (int j = 0; j < 4; j++) { int c = wcnt[j]; wcnt[j] = sum; sum += c; }
        wcnt[4] = sum;
    }
    __syncthreads();
    const int nkeep = wcnt[4];
    if (kflag) {
        int pos = wcnt[wid] + __popc(bal & ((1u << lane) - 1u));
        offbuf[pos] = tid * ROW_BYTES;
    }
    __syncthreads();

    // warp w owns kept rows at compacted positions w, w+4, w+8, ...
    // each row read CONTIGUOUSLY: lane covers [lane*16 + j*512], j=0..3
    const char* xbase = reinterpret_cast<const char*>(
        x + ((size_t)b * T_DIM + t0) * D_DIM) + lane * 16;

    float4 a0 = make_float4(0.f, 0.f, 0.f, 0.f);
    float4 a1 = a0, a2 = a0, a3 = a0;

    const int cnt = (nkeep + 3 - wid) >> 2;   // this warp's row count
    if (cnt > 0) {
        const char* p = xbase + offbuf[wid];
        float4 c0 = __ldcs(reinterpret_cast<const float4*>(p + 0));
        float4 c1 = __ldcs(reinterpret_cast<const float4*>(p + 512));
        float4 c2 = __ldcs(reinterpret_cast<const float4*>(p + 1024));
        float4 c3 = __ldcs(reinterpret_cast<const float4*>(p + 1536));
        for (int i = 1; i < cnt; i++) {
            const char* q = xbase + offbuf[i * 4 + wid];
            float4 n0 = __ldcs(reinterpret_cast<const float4*>(q + 0));
            float4 n1 = __ldcs(reinterpret_cast<const float4*>(q + 512));
            float4 n2 = __ldcs(reinterpret_cast<const float4*>(q + 1024));
            float4 n3 = __ldcs(reinterpret_cast<const float4*>(q + 1536));
            ACC4(a0, c0); ACC4(a1, c1); ACC4(a2, c2); ACC4(a3, c3);
            c0 = n0; c1 = n1; c2 = n2; c3 = n3;
        }
        ACC4(a0, c0); ACC4(a1, c1); ACC4(a2, c2); ACC4(a3, c3);
    }

    // cross-warp reduction: warp w's a_j covers D-bytes [j*512 + lane*16).
    // final thread t owns D-bytes [t*16): piece j = t/32, lane = t%32.
    sacc[wid][0 * 32 + lane] = a0;
    sacc[wid][1 * 32 + lane] = a1;
    sacc[wid][2 * 32 + lane] = a2;
    sacc[wid][3 * 32 + lane] = a3;
    __syncthreads();

    float4 r = sacc[0][tid];
    ACC4(r, sacc[1][tid]);
    ACC4(r, sacc[2][tid]);
    ACC4(r, sacc[3][tid]);

    reinterpret_cast<float4*>(g_partial)[(size_t)(b * S_SPLIT + s) * DSTRIDE + tid] = r;
    if (tid == 0) g_count[b * S_SPLIT + s] = (float)nkeep;

    // ALL warps must finish partial stores before this CTA arrives.
    __syncthreads();
    __threadfence();
    if (tid == 0) {
        int v = atomicAdd(&g_sem[b], 1);
        isLast = (v == S_SPLIT - 1);
    }
    __syncthreads();

    if (isLast) {
        float denom = 0.f;
        #pragma unroll 8
        for (int ss = 0; ss < S_SPLIT; ss++) denom += g_count[b * S_SPLIT + ss];

        float4 r0 = make_float4(0.f, 0.f, 0.f, 0.f);
        float4 r1 = make_float4(0.f, 0.f, 0.f, 0.f);
        const float4* gp = reinterpret_cast<const float4*>(g_partial);
        #pragma unroll 8
        for (int ss = 0; ss < S_SPLIT; ss += 2) {
            float4 v0 = gp[(size_t)(b * S_SPLIT + ss) * DSTRIDE + tid];
            float4 v1 = gp[(size_t)(b * S_SPLIT + ss + 1) * DSTRIDE + tid];
            ACC4(r0, v0); ACC4(r1, v1);
        }
        ACC4(r0, r1);
        float inv = 1.f / denom;
        r0.x *= inv; r0.y *= inv; r0.z *= inv; r0.w *= inv;
        reinterpret_cast<float4*>(out)[(size_t)b * DSTRIDE + tid] = r0;

        if (tid == 0) g_sem[b] = 0;  // reset for next graph replay
    }
}

extern "C" void kernel_launch(void* const* d_in, const int* in_sizes, int n_in,
                              void* d_out, int out_size) {
    const float* x = (const float*)d_in[0];
    const int* mask = (const int*)d_in[1];
    float* out = (float*)d_out;

    dim3 grid(S_SPLIT, B_DIM);
    mp_fused_kernel<<<grid, TPB>>>(x, mask, out);
}